// round 12
// baseline (speedup 1.0000x reference)
#include <cuda_runtime.h>
#include <cuda_fp16.h>
#include <cstdint>
#include <math.h>

// Problem constants
#define BB   32
#define TT   32
#define HH   28
#define WW   28
#define FF   48
#define UU   8
#define EPSB 1e-3f
#define NFRAMES (BB*TT)            // 1024
#define FRAME_PIX (HH*WW)          // 784
#define PW   30                    // padded width
#define PROWS (PW*PW)              // 900 padded pixel-rows per frame

// ---------------------------------------------------------------------------
// Warp-MMA helpers
// ---------------------------------------------------------------------------
__device__ __forceinline__ uint32_t smem_u32(const void* p) {
    return (uint32_t)__cvta_generic_to_shared(p);
}
__device__ __forceinline__ void ldmx4(uint32_t a[4], uint32_t addr) {
    asm volatile("ldmatrix.sync.aligned.m8n8.x4.shared.b16 {%0,%1,%2,%3}, [%4];"
                 : "=r"(a[0]), "=r"(a[1]), "=r"(a[2]), "=r"(a[3]) : "r"(addr));
}
__device__ __forceinline__ void mma_fp16(float c[4], const uint32_t a[4],
                                         uint32_t b0, uint32_t b1) {
    asm volatile("mma.sync.aligned.m16n8k16.row.col.f32.f16.f16.f32 "
                 "{%0,%1,%2,%3},{%4,%5,%6,%7},{%8,%9},{%0,%1,%2,%3};"
                 : "+f"(c[0]), "+f"(c[1]), "+f"(c[2]), "+f"(c[3])
                 : "r"(a[0]), "r"(a[1]), "r"(a[2]), "r"(a[3]), "r"(b0), "r"(b1));
}
__device__ __forceinline__ void cpa16(uint32_t dst, const void* src, uint32_t srcbytes) {
    asm volatile("cp.async.cg.shared.global [%0], [%1], 16, %2;"
                 :: "r"(dst), "l"(src), "r"(srcbytes));
}
__device__ __forceinline__ void cpa4(uint32_t dst, const void* src) {
    asm volatile("cp.async.ca.shared.global [%0], [%1], 4;"
                 :: "r"(dst), "l"(src));
}
#define CPA_COMMIT() asm volatile("cp.async.commit_group;" ::: "memory")
#define CPA_WAIT(n)  asm volatile("cp.async.wait_group %0;" :: "n"(n) : "memory")

// ---------------------------------------------------------------------------
// Scratch
// ---------------------------------------------------------------------------
__device__ __align__(16) __half g_a2[NFRAMES * PROWS * FF];
__device__ __align__(16) uint32_t g_bfrag[2][27 * 6 * 64];  // fp16x2 fragments
__device__ float g_feats[NFRAMES * 4 * FF];   // per-(frame,quarter) pooled partials

// ---------------------------------------------------------------------------
// Kernel 0: pre-fragment conv weights (once per run)
// ---------------------------------------------------------------------------
__global__ void prep_kernel(const float* __restrict__ w2,
                            const float* __restrict__ w3)
{
    const float* w = (blockIdx.x == 0) ? w2 : w3;
    uint32_t* dst = g_bfrag[blockIdx.x];
    for (int i = threadIdx.x; i < 162 * 64; i += 256) {
        const int group = i >> 6;
        const int slot  = i & 63;
        const int l     = slot >> 1;
        const int reg   = slot & 1;
        const int tapkc = group / 6;
        const int nt    = group - tapkc * 6;
        const int tap   = tapkc / 3;
        const int kc    = tapkc - tap * 3;
        const int n     = nt * 8 + (l >> 2);
        const int k     = kc * 16 + (l & 3) * 2 + reg * 8;
        const __half h0 = __float2half_rn(w[(tap * FF + k)     * FF + n]);
        const __half h1 = __float2half_rn(w[(tap * FF + k + 1) * FF + n]);
        dst[i] = (uint32_t)__half_as_ushort(h0) | ((uint32_t)__half_as_ushort(h1) << 16);
    }
}

// ---------------------------------------------------------------------------
// Shared conv48 geometry (quarter-frame items)
// ---------------------------------------------------------------------------
#define Q_ROWS    225
#define A_STRIDE  112
#define MT_MAX    14                            // last valid tile index (15 tiles)
#define T_PER_W   2
#define GRID_CONV 296                           // 2 CTAs/SM x 148
#define N_ITEMS   (NFRAMES * 4)                 // 4096 quarter-frames
#define B_BYTES   (27 * 6 * 64 * 4)             // 41472

// ---------------------------------------------------------------------------
// Kernel A (phase 0 FUSED): conv1 computed in-smem + conv2 via mma.sync.
// Persistent, 2 CTAs/SM, single A buffer (fill is synchronous compute; the
// co-resident CTA overlaps). x frame staged via cp.async one item ahead.
// ---------------------------------------------------------------------------
#define P0_SLAB   302                           // max accessed slab row = 301
#define P0_ABYTES (P0_SLAB * A_STRIDE)          // 33824
#define P0_OFF_A  0
#define P0_OFF_B  P0_ABYTES                     // 33824
#define P0_OFF_BI (P0_OFF_B + B_BYTES)          // 75296
#define P0_OFF_XF (P0_OFF_BI + 192)             // 75488 (900 fp32)
#define P0_OFF_W1 (P0_OFF_XF + 3600)            // 79088 (216 float2)
#define P0_OFF_B1 (P0_OFF_W1 + 1728)            // 80816 (24 float2)
#define P0_SMEM   (P0_OFF_B1 + 192)             // 81008

__global__ void __launch_bounds__(256, 2)
convmm_fused0(const float* __restrict__ x,
              const float* __restrict__ w1,
              const float* __restrict__ b1,
              const uint32_t* __restrict__ bfrag,
              const float* __restrict__ bias)
{
    extern __shared__ __align__(16) char smem[];

    const int bid  = blockIdx.x;
    const int tid  = threadIdx.x;
    const int wid  = tid >> 5;
    const int lane = tid & 31;
    const uint32_t smb = smem_u32(smem);
    const int nItems = (N_ITEMS - bid + GRID_CONV - 1) / GRID_CONV;

    float*  s_bias = (float*)(smem + P0_OFF_BI);
    float*  s_xf   = (float*)(smem + P0_OFF_XF);
    float2* s_w1   = (float2*)(smem + P0_OFF_W1);
    float2* s_b1   = (float2*)(smem + P0_OFF_B1);

    if (tid < FF) s_bias[tid] = bias[tid];
    for (int i = tid; i < 9 * 24; i += 256) s_w1[i] = ((const float2*)w1)[i];
    if (tid < 24) s_b1[tid] = ((const float2*)b1)[tid];
    // zero ONLY halo of padded x image (interior written by cp.async per item)
    for (int i = tid; i < PROWS; i += 256) {
        const int rd = i / PW, rm = i - rd * PW;
        if (rd == 0 || rd == PW - 1 || rm == 0 || rm == PW - 1) s_xf[i] = 0.f;
    }

    // B fragments + first item's x: one async group
    for (int i = tid; i < B_BYTES / 16; i += 256)
        cpa16(smb + P0_OFF_B + i * 16, (const char*)bfrag + i * 16, 16);
    if (nItems > 0) {
        const float* xsrc = x + (size_t)(bid >> 2) * FRAME_PIX;
        for (int i = tid; i < FRAME_PIX; i += 256) {
            const int pr = i / WW, pc = i - pr * WW;
            cpa4(smb + P0_OFF_XF + ((pr + 1) * PW + pc + 1) * 4, xsrc + i);
        }
    }
    CPA_COMMIT();

    const uint32_t laneoff = (uint32_t)((lane & 15) * A_STRIDE + ((lane >> 4) << 4));
    const uint32_t* s_b = (const uint32_t*)(smem + P0_OFF_B);

    for (int k = 0; k < nItems; ++k) {
        const int item  = bid + GRID_CONV * k;
        const int frame = item >> 2;
        const int rbase = (item & 3) * Q_ROWS;

        CPA_WAIT(0);
        __syncthreads();     // x(k) landed; prev item's A reads done

        // ---- conv1 fill: compute A slab (fp16x2) from padded x image ----
        for (int idx = tid; idx < P0_SLAB * 24; idx += 256) {
            const int s   = idx / 24;
            const int co2 = idx - s * 24;
            const int r   = rbase - 31 + s;
            uint32_t val = 0u;
            if (r >= 31 && r < PROWS) {
                const int rd = r / PW, rm = r - rd * PW;
                if (rd >= 1 && rd <= HH && rm >= 1 && rm <= WW) {
                    float2 acc = s_b1[co2];
                    const int base = r - 31;
                    #pragma unroll
                    for (int t = 0; t < 9; ++t) {
                        const float v = s_xf[base + (t / 3) * PW + (t % 3)];
                        const float2 fw = s_w1[t * 24 + co2];
                        acc.x += v * fw.x;
                        acc.y += v * fw.y;
                    }
                    const __half2 hv = __floats2half2_rn(fmaxf(acc.x, 0.f), fmaxf(acc.y, 0.f));
                    val = *(const uint32_t*)&hv;
                }
            }
            *(uint32_t*)(smem + P0_OFF_A + s * A_STRIDE + co2 * 4) = val;
        }
        __syncthreads();     // A slab ready; all x reads done

        // prefetch next item's x frame
        if (k + 1 < nItems) {
            const float* xsrc = x + (size_t)((item + GRID_CONV) >> 2) * FRAME_PIX;
            for (int i = tid; i < FRAME_PIX; i += 256) {
                const int pr = i / WW, pc = i - pr * WW;
                cpa4(smb + P0_OFF_XF + ((pr + 1) * PW + pc + 1) * 4, xsrc + i);
            }
        }
        CPA_COMMIT();

        // ---- MMA loop (merged tapkc, fully unrolled; skip warp-7 dup) ----
        int mtv[T_PER_W];
        uint32_t abase[T_PER_W];
        #pragma unroll
        for (int i = 0; i < T_PER_W; ++i) {
            int mt = wid + 8 * i;
            mtv[i] = mt;
            if (mt > MT_MAX) mt = MT_MAX;
            abase[i] = smb + P0_OFF_A + (uint32_t)((31 + mt * 16) * A_STRIDE) + laneoff;
        }

        float C[T_PER_W][6][4];
        #pragma unroll
        for (int i = 0; i < T_PER_W; ++i)
            #pragma unroll
            for (int nt = 0; nt < 6; ++nt) {
                C[i][nt][0] = 0.f; C[i][nt][1] = 0.f; C[i][nt][2] = 0.f; C[i][nt][3] = 0.f;
            }

        #pragma unroll
        for (int g = 0; g < 27; ++g) {
            const int tap = g / 3, kc = g - tap * 3;
            const int dy = tap / 3;
            const int aoff = ((dy - 1) * PW + (tap - dy * 3) - 1) * A_STRIDE + kc * 32;
            uint2 BW[6];
            const int bbase = g * 6 * 64 + lane * 2;
            #pragma unroll
            for (int nt = 0; nt < 6; ++nt)
                BW[nt] = *(const uint2*)(s_b + bbase + nt * 64);
            #pragma unroll
            for (int i = 0; i < T_PER_W; ++i) {
                if (i == 0 || mtv[i] <= MT_MAX) {
                    uint32_t a[4];
                    ldmx4(a, abase[i] + (uint32_t)aoff);
                    #pragma unroll
                    for (int nt = 0; nt < 6; ++nt)
                        mma_fp16(C[i][nt], a, BW[nt].x, BW[nt].y);
                }
            }
        }

        // ---- Epilogue: bias+ReLU, fp16 store to g_a2 ----
        #pragma unroll
        for (int i = 0; i < T_PER_W; ++i) {
            if (mtv[i] > MT_MAX) continue;
            #pragma unroll
            for (int rh = 0; rh < 2; ++rh) {
                const int r = rbase + mtv[i] * 16 + (lane >> 2) + rh * 8;
                if (r < PROWS) {
                    uint32_t* d = (uint32_t*)(g_a2 + ((size_t)frame * PROWS + r) * FF);
                    #pragma unroll
                    for (int nt = 0; nt < 6; ++nt) {
                        const int co = nt * 8 + (lane & 3) * 2;
                        const __half h0 = __float2half_rn(fmaxf(C[i][nt][rh * 2]     + s_bias[co],     0.f));
                        const __half h1 = __float2half_rn(fmaxf(C[i][nt][rh * 2 + 1] + s_bias[co + 1], 0.f));
                        d[co >> 1] = (uint32_t)__half_as_ushort(h0) | ((uint32_t)__half_as_ushort(h1) << 16);
                    }
                }
            }
        }
        __syncthreads();     // A reads complete before next fill overwrites
    }
}

// ---------------------------------------------------------------------------
// Kernel B (phase 1): conv3 + global-avg-pool. Persistent double-buffered
// cp.async slabs (reads g_a2), 2 CTAs/SM. Merged unrolled MMA loop.
// ---------------------------------------------------------------------------
#define P1_SLAB   304
#define P1_ABYTES (P1_SLAB * A_STRIDE)          // 34048
#define P1_OFF_A0 0
#define P1_OFF_A1 P1_ABYTES                     // 34048
#define P1_OFF_B  (2 * P1_ABYTES)               // 68096
#define P1_OFF_BI (P1_OFF_B + B_BYTES)          // 109568
#define P1_SMEM   (P1_OFF_BI + 192)             // 109760

__device__ __forceinline__ void issue_slab(uint32_t dst, const __half* __restrict__ in,
                                           int item, int tid)
{
    const int frame = item >> 2;
    const int rbase = (item & 3) * Q_ROWS;
    const char* src = (const char*)(in + (size_t)frame * PROWS * FF);
    for (int i = tid; i < P1_SLAB * 7; i += 256) {
        const int s   = i / 7;
        const int blk = i - s * 7;
        const int r   = rbase - 31 + s;
        bool valid = false;
        if (r >= 0 && r < PROWS && blk < 6) {
            const int rd = r / PW, rm = r - rd * PW;
            valid = (rd >= 1 && rd <= HH && rm >= 1 && rm <= WW);
        }
        const long off = valid ? ((long)r * 96 + blk * 16) : 0;
        cpa16(dst + s * A_STRIDE + blk * 16, src + off, valid ? 16u : 0u);
    }
}

__global__ void __launch_bounds__(256, 2)
convmm_pool1(const __half* __restrict__ in,
             const uint32_t* __restrict__ bfrag,
             const float* __restrict__ bias)
{
    extern __shared__ __align__(16) char smem[];
    __shared__ float s_pool[8 * FF];

    const int bid  = blockIdx.x;
    const int tid  = threadIdx.x;
    const int wid  = tid >> 5;
    const int lane = tid & 31;
    const uint32_t smb = smem_u32(smem);
    const int nItems = (N_ITEMS - bid + GRID_CONV - 1) / GRID_CONV;

    float* s_bias = (float*)(smem + P1_OFF_BI);
    if (tid < FF) s_bias[tid] = bias[tid];

    for (int i = tid; i < B_BYTES / 16; i += 256)
        cpa16(smb + P1_OFF_B + i * 16, (const char*)bfrag + i * 16, 16);
    if (nItems > 0) issue_slab(smb + P1_OFF_A0, in, bid, tid);
    CPA_COMMIT();

    const uint32_t laneoff = (uint32_t)((lane & 15) * A_STRIDE + ((lane >> 4) << 4));
    const uint32_t* s_b = (const uint32_t*)(smem + P1_OFF_B);

    for (int k = 0; k < nItems; ++k) {
        const int item  = bid + GRID_CONV * k;
        const int frame = item >> 2;
        const int rbase = (item & 3) * Q_ROWS;
        const uint32_t abuf = smb + ((k & 1) ? P1_OFF_A1 : P1_OFF_A0);

        if (k + 1 < nItems) {
            issue_slab(smb + ((k & 1) ? P1_OFF_A0 : P1_OFF_A1), in, item + GRID_CONV, tid);
            CPA_COMMIT();
            CPA_WAIT(1);
        } else {
            CPA_WAIT(0);
        }
        __syncthreads();

        int mtv[T_PER_W];
        uint32_t abase[T_PER_W];
        #pragma unroll
        for (int i = 0; i < T_PER_W; ++i) {
            int mt = wid + 8 * i;
            mtv[i] = mt;
            if (mt > MT_MAX) mt = MT_MAX;
            abase[i] = abuf + (uint32_t)((31 + mt * 16) * A_STRIDE) + laneoff;
        }

        float C[T_PER_W][6][4];
        #pragma unroll
        for (int i = 0; i < T_PER_W; ++i)
            #pragma unroll
            for (int nt = 0; nt < 6; ++nt) {
                C[i][nt][0] = 0.f; C[i][nt][1] = 0.f; C[i][nt][2] = 0.f; C[i][nt][3] = 0.f;
            }

        #pragma unroll
        for (int g = 0; g < 27; ++g) {
            const int tap = g / 3, kc = g - tap * 3;
            const int dy = tap / 3;
            const int aoff = ((dy - 1) * PW + (tap - dy * 3) - 1) * A_STRIDE + kc * 32;
            uint2 BW[6];
            const int bbase = g * 6 * 64 + lane * 2;
            #pragma unroll
            for (int nt = 0; nt < 6; ++nt)
                BW[nt] = *(const uint2*)(s_b + bbase + nt * 64);
            #pragma unroll
            for (int i = 0; i < T_PER_W; ++i) {
                if (i == 0 || mtv[i] <= MT_MAX) {
                    uint32_t a[4];
                    ldmx4(a, abase[i] + (uint32_t)aoff);
                    #pragma unroll
                    for (int nt = 0; nt < 6; ++nt)
                        mma_fp16(C[i][nt], a, BW[nt].x, BW[nt].y);
                }
            }
        }

        // ---- Epilogue: bias+ReLU, pool owned interior rows ----
        float pool[6][2];
        #pragma unroll
        for (int nt = 0; nt < 6; ++nt) { pool[nt][0] = 0.f; pool[nt][1] = 0.f; }

        #pragma unroll
        for (int i = 0; i < T_PER_W; ++i) {
            if (mtv[i] > MT_MAX) continue;
            #pragma unroll
            for (int rh = 0; rh < 2; ++rh) {
                const int r = rbase + mtv[i] * 16 + (lane >> 2) + rh * 8;
                bool valid = false;
                if ((r - rbase) < Q_ROWS && r < PROWS) {
                    const int rd = r / PW, rm = r - rd * PW;
                    valid = (rd >= 1 && rd <= HH && rm >= 1 && rm <= WW);
                }
                if (valid) {
                    #pragma unroll
                    for (int nt = 0; nt < 6; ++nt) {
                        const int co = nt * 8 + (lane & 3) * 2;
                        pool[nt][0] += fmaxf(C[i][nt][rh * 2]     + s_bias[co],     0.f);
                        pool[nt][1] += fmaxf(C[i][nt][rh * 2 + 1] + s_bias[co + 1], 0.f);
                    }
                }
            }
        }

        #pragma unroll
        for (int nt = 0; nt < 6; ++nt) {
            #pragma unroll
            for (int e = 0; e < 2; ++e) {
                float v = pool[nt][e];
                v += __shfl_xor_sync(0xffffffffu, v, 4);
                v += __shfl_xor_sync(0xffffffffu, v, 8);
                v += __shfl_xor_sync(0xffffffffu, v, 16);
                if ((lane >> 2) == 0)
                    s_pool[wid * FF + nt * 8 + lane * 2 + e] = v;
            }
        }
        __syncthreads();
        if (tid < FF) {
            float s = 0.f;
            #pragma unroll
            for (int ww = 0; ww < 8; ++ww) s += s_pool[ww * FF + tid];
            g_feats[(frame * 4 + (item & 3)) * FF + tid] = s;
        }
        __syncthreads();   // all reads of abuf done before it is refilled
    }
}

// ---------------------------------------------------------------------------
// Kernel 4: LSTM + BN2 + head. One warp per batch element.
// ---------------------------------------------------------------------------
__device__ __forceinline__ float fsig(float x)  { return __fdividef(1.f, 1.f + __expf(-x)); }
__device__ __forceinline__ float ftanh(float x) { return 1.f - __fdividef(2.f, __expf(2.f * x) + 1.f); }

__global__ void __launch_bounds__(32, 1)
lstm_kernel(const float* __restrict__ wf,  const float* __restrict__ bf,
            const float* __restrict__ wi1, const float* __restrict__ bi1,
            const float* __restrict__ wi2, const float* __restrict__ bi2,
            const float* __restrict__ wo,  const float* __restrict__ bo,
            const float* __restrict__ bn1_g, const float* __restrict__ bn1_b,
            const float* __restrict__ bn1_m, const float* __restrict__ bn1_v,
            const float* __restrict__ bn2_g, const float* __restrict__ bn2_b,
            const float* __restrict__ bn2_m, const float* __restrict__ bn2_v,
            const float* __restrict__ w_out, const float* __restrict__ b_out,
            float* __restrict__ out)
{
    __shared__ float s_x[TT][FF];
    __shared__ float s_g[TT][32];
    __shared__ float s_sc1[FF], s_sh1[FF];

    const int b    = blockIdx.x;
    const int lane = threadIdx.x;
    const int u    = lane & 7;

    const float* Wg = (lane < 8) ? wf : (lane < 16) ? wi1 : (lane < 24) ? wi2 : wo;
    const float* Bg = (lane < 8) ? bf : (lane < 16) ? bi1 : (lane < 24) ? bi2 : bo;
    float wcol[FF + UU];
    #pragma unroll
    for (int k = 0; k < FF + UU; ++k) wcol[k] = Wg[k * UU + u];
    const float bgate = Bg[u];

    for (int co = lane; co < FF; co += 32) {
        const float sc = bn1_g[co] * rsqrtf(bn1_v[co] + EPSB);
        s_sc1[co] = sc * (1.f / (float)FRAME_PIX);
        s_sh1[co] = bn1_b[co] - bn1_m[co] * sc;
    }
    __syncwarp();

    for (int i = lane; i < TT * FF; i += 32) {
        const int t = i / FF, co = i - t * FF;
        const int fr = (b << 5) + t;
        const float ps = g_feats[(fr * 4 + 0) * FF + co] + g_feats[(fr * 4 + 1) * FF + co]
                       + g_feats[(fr * 4 + 2) * FF + co] + g_feats[(fr * 4 + 3) * FF + co];
        s_x[t][co] = ps * s_sc1[co] + s_sh1[co];
    }
    __syncwarp();

    #pragma unroll 4
    for (int t = 0; t < TT; ++t) {
        float a0 = 0.f, a1 = 0.f, a2 = 0.f, a3 = 0.f;
        #pragma unroll
        for (int k = 0; k < FF; k += 4) {
            a0 += s_x[t][k]     * wcol[k];
            a1 += s_x[t][k + 1] * wcol[k + 1];
            a2 += s_x[t][k + 2] * wcol[k + 2];
            a3 += s_x[t][k + 3] * wcol[k + 3];
        }
        s_g[t][lane] = bgate + ((a0 + a1) + (a2 + a3));
    }
    __syncwarp();

    const float sc2  = bn2_g[u] * rsqrtf(bn2_v[u] + EPSB);
    const float coef = sc2 * w_out[u];
    float outc = b_out[0];
    #pragma unroll
    for (int j = 0; j < UU; ++j) {
        const float s2 = bn2_g[j] * rsqrtf(bn2_v[j] + EPSB);
        outc += (bn2_b[j] - bn2_m[j] * s2) * w_out[j];
    }

    float c = 0.f, h = 0.f;
    for (int t = 0; t < TT; ++t) {
        float a = s_g[t][lane];
        #pragma unroll
        for (int j = 0; j < UU; ++j)
            a += __shfl_sync(0xffffffffu, h, j) * wcol[FF + j];

        const float fg = fsig (__shfl_sync(0xffffffffu, a, u));
        const float ig = fsig (__shfl_sync(0xffffffffu, a, u + 8));
        const float gg = ftanh(__shfl_sync(0xffffffffu, a, u + 16));
        const float og = fsig (__shfl_sync(0xffffffffu, a, u + 24));
        c = fg * c + ig * gg;
        h = og * ftanh(c);

        float p = h * coef;
        p += __shfl_xor_sync(0xffffffffu, p, 1);
        p += __shfl_xor_sync(0xffffffffu, p, 2);
        p += __shfl_xor_sync(0xffffffffu, p, 4);
        if (lane == 0) out[(b << 5) + t] = p + outc;
    }
}

// ---------------------------------------------------------------------------
// Launch
// ---------------------------------------------------------------------------
extern "C" void kernel_launch(void* const* d_in, const int* in_sizes, int n_in,
                              void* d_out, int out_size)
{
    const float* x     = (const float*)d_in[0];
    const float* w1    = (const float*)d_in[1];
    const float* b1    = (const float*)d_in[2];
    const float* w2    = (const float*)d_in[3];
    const float* b2    = (const float*)d_in[4];
    const float* w3    = (const float*)d_in[5];
    const float* b3    = (const float*)d_in[6];
    const float* bn1_g = (const float*)d_in[7];
    const float* bn1_b = (const float*)d_in[8];
    const float* bn1_m = (const float*)d_in[9];
    const float* bn1_v = (const float*)d_in[10];
    const float* wf    = (const float*)d_in[11];
    const float* bf    = (const float*)d_in[12];
    const float* wi1   = (const float*)d_in[13];
    const float* bi1   = (const float*)d_in[14];
    const float* wi2   = (const float*)d_in[15];
    const float* bi2   = (const float*)d_in[16];
    const float* wo    = (const float*)d_in[17];
    const float* bo    = (const float*)d_in[18];
    const float* bn2_g = (const float*)d_in[19];
    const float* bn2_b = (const float*)d_in[20];
    const float* bn2_m = (const float*)d_in[21];
    const float* bn2_v = (const float*)d_in[22];
    const float* w_out = (const float*)d_in[23];
    const float* b_out = (const float*)d_in[24];
    float* out = (float*)d_out;

    cudaFuncSetAttribute(convmm_fused0, cudaFuncAttributeMaxDynamicSharedMemorySize, P0_SMEM);
    cudaFuncSetAttribute(convmm_pool1,  cudaFuncAttributeMaxDynamicSharedMemorySize, P1_SMEM);

    __half* a2 = nullptr;
    uint32_t* bfrag = nullptr;
    cudaGetSymbolAddress((void**)&a2, g_a2);
    cudaGetSymbolAddress((void**)&bfrag, g_bfrag);

    prep_kernel<<<2, 256>>>(w2, w3);
    convmm_fused0<<<GRID_CONV, 256, P0_SMEM>>>(x, w1, b1, bfrag, b2);
    convmm_pool1<<<GRID_CONV, 256, P1_SMEM>>>(a2, bfrag + 27 * 6 * 64, b3);
    lstm_kernel<<<BB, 32>>>(wf, bf, wi1, bi1, wi2, bi2, wo, bo,
                            bn1_g, bn1_b, bn1_m, bn1_v,
                            bn2_g, bn2_b, bn2_m, bn2_v,
                            w_out, b_out, out);
}